// round 16
// baseline (speedup 1.0000x reference)
#include <cuda_runtime.h>
#include <cuda_bf16.h>
#include <stdint.h>
#include <math.h>

#define NH     8
#define BATCH  4
#define SEQ    1024
#define DMODEL 512
#define DH     64
#define SCALEQ 0.04419417382415922f  // 1/sqrt(512)

// ---- scratch (device globals; no allocation allowed) ----
__device__ __nv_bfloat16 gAhi[4096 * 512];   // emb hi
__device__ __nv_bfloat16 gAlo[4096 * 512];   // emb lo
__device__ __nv_bfloat16 gWhi[1536 * 512];   // W^T hi  [n][k]
__device__ __nv_bfloat16 gWlo[1536 * 512];   // W^T lo
__device__ __nv_bfloat16 gQhi[BATCH * NH * SEQ * DH];
__device__ __nv_bfloat16 gQlo[BATCH * NH * SEQ * DH];
// K in mma B-fragment layout: u32[bh][jb(128)][kshalf(2)][lane(32)][slot(4)]
__device__ uint32_t gKfh[BATCH * NH * 128 * 2 * 32 * 4];
__device__ uint32_t gKfl[BATCH * NH * 128 * 2 * 32 * 4];
__device__ float gVW[BATCH * NH * SEQ];

// ============================================================
// helpers
// ============================================================
__device__ __forceinline__ uint32_t smem_u32(const void* p) {
    uint32_t a;
    asm("{ .reg .u64 t; cvta.to.shared.u64 t, %1; cvt.u32.u64 %0, t; }"
        : "=r"(a) : "l"(p));
    return a;
}
__device__ __forceinline__ void split_bf16(float x, __nv_bfloat16& h, __nv_bfloat16& l) {
    h = __float2bfloat16(x);
    l = __float2bfloat16(x - __bfloat162float(h));
}
__device__ __forceinline__ uint32_t pack2(__nv_bfloat16 a, __nv_bfloat16 b) {
    __nv_bfloat162 t; t.x = a; t.y = b;
    return *(uint32_t*)&t;
}
__device__ __forceinline__ void mma_bf16(float c[4], uint32_t a0, uint32_t a1,
                                         uint32_t a2, uint32_t a3,
                                         uint32_t b0, uint32_t b1) {
    asm volatile(
        "mma.sync.aligned.m16n8k16.row.col.f32.bf16.bf16.f32 "
        "{%0,%1,%2,%3}, {%4,%5,%6,%7}, {%8,%9}, {%0,%1,%2,%3};"
        : "+f"(c[0]), "+f"(c[1]), "+f"(c[2]), "+f"(c[3])
        : "r"(a0), "r"(a1), "r"(a2), "r"(a3), "r"(b0), "r"(b1));
}
__device__ __forceinline__ void ldm_x4(uint32_t r[4], uint32_t addr) {
    asm volatile("ldmatrix.sync.aligned.m8n8.x4.shared.b16 {%0,%1,%2,%3}, [%4];"
                 : "=r"(r[0]), "=r"(r[1]), "=r"(r[2]), "=r"(r[3]) : "r"(addr));
}
__device__ __forceinline__ void cp_async16(uint32_t dst, const void* src) {
    asm volatile("cp.async.cg.shared.global [%0], [%1], 16;" :: "r"(dst), "l"(src));
}
__device__ __forceinline__ void cp_commit() {
    asm volatile("cp.async.commit_group;");
}

// ============================================================
// P1 (merged): blocks 0..2047 split emb; blocks 2048..2815
// transpose+split W.
// ============================================================
__global__ __launch_bounds__(256) void prep_all(const float* __restrict__ emb,
                                                const float* __restrict__ W)
{
    if (blockIdx.x < 2048) {
        size_t i = ((size_t)blockIdx.x * 256 + threadIdx.x) * 4;
        float4 v = *(const float4*)(emb + i);
        __nv_bfloat16 h[4], l[4];
        split_bf16(v.x, h[0], l[0]); split_bf16(v.y, h[1], l[1]);
        split_bf16(v.z, h[2], l[2]); split_bf16(v.w, h[3], l[3]);
        uint2 uh = make_uint2(pack2(h[0], h[1]), pack2(h[2], h[3]));
        uint2 ul = make_uint2(pack2(l[0], l[1]), pack2(l[2], l[3]));
        *(uint2*)(gAhi + i) = uh;
        *(uint2*)(gAlo + i) = ul;
    } else {
        __shared__ float t[32][33];
        const int bi = blockIdx.x - 2048;       // 0..767
        const int n0 = (bi % 48) * 32, k0 = (bi / 48) * 32;
        const int tx = threadIdx.x & 31, ty = threadIdx.x >> 5;
#pragma unroll
        for (int it = 0; it < 4; it++)
            t[ty + it * 8][tx] = W[(size_t)(k0 + ty + it * 8) * 1536 + n0 + tx];
        __syncthreads();
#pragma unroll
        for (int it = 0; it < 4; it++) {
            int n = ty + it * 8;
            float v = t[tx][n];
            __nv_bfloat16 h, l;
            split_bf16(v, h, l);
            gWhi[(size_t)(n0 + n) * 512 + k0 + tx] = h;
            gWlo[(size_t)(n0 + n) * 512 + k0 + tx] = l;
        }
    }
}

// ============================================================
// K1: qkv GEMM. 4-stage cp.async ring (BK=16), ONE sync/chunk.
// ============================================================
#define TS2 24
#define TILE2_B (128 * TS2 * 2)          // 6144 B
#define STAGE2_B (4 * TILE2_B)           // 24576 B
#define NSTAGE 4
#define QKV_SMEM (NSTAGE * STAGE2_B + 1024)

__global__ __launch_bounds__(256, 2) void qkv_cp(const float* __restrict__ bias,
                                                 const float* __restrict__ wf)
{
    extern __shared__ char sm[];
    float* bias_sm = (float*)(sm + NSTAGE * STAGE2_B);
    float* wf_sm   = (float*)(sm + NSTAGE * STAGE2_B + 512);
    const uint32_t base = smem_u32(sm);

    const int tid = threadIdx.x;
    const int wid = tid >> 5, lane = tid & 31;
    const int wM = wid & 3, wN = wid >> 2;
    const int bx = blockIdx.x, by = blockIdx.y;
    const int lr = lane & 7, lg = lane >> 3;

    if (tid < 128) {
        bias_sm[tid] = bias[bx * 128 + tid];
        if (bx >= 8) wf_sm[tid] = wf[(bx - 8) * 128 + tid];
    }

    uint32_t offA[2], offB[4];
#pragma unroll
    for (int mt = 0; mt < 2; mt++) {
        int row = wM * 32 + mt * 16 + (lg & 1) * 8 + lr;
        offA[mt] = row * (TS2 * 2) + (lg >> 1) * 16;
    }
#pragma unroll
    for (int p = 0; p < 4; p++) {
        int n = wN * 64 + p * 16 + (lg >> 1) * 8 + lr;
        offB[p] = n * (TS2 * 2) + (lg & 1) * 16;
    }

    const __nv_bfloat16* srcs[4] = {
        gAhi + (size_t)(by * 128) * 512,
        gAlo + (size_t)(by * 128) * 512,
        gWhi + (size_t)(bx * 128) * 512,
        gWlo + (size_t)(bx * 128) * 512
    };

    float c[2][8][4];
#pragma unroll
    for (int mt = 0; mt < 2; mt++)
#pragma unroll
        for (int nt = 0; nt < 8; nt++)
#pragma unroll
            for (int j = 0; j < 4; j++) c[mt][nt][j] = 0.f;

    auto issue = [&](int ch) {
        if (ch < 32) {
            const uint32_t sb = base + (ch & 3) * STAGE2_B;
#pragma unroll
            for (int l = 0; l < 4; l++) {
                int idx = tid + l * 256;
                int tile = idx >> 8;
                int rem = idx & 255;
                int row = rem >> 1, half = rem & 1;
                uint32_t dst = sb + tile * TILE2_B + row * (TS2 * 2) + half * 16;
                const __nv_bfloat16* src = srcs[tile] + (size_t)row * 512 + ch * 16 + half * 8;
                cp_async16(dst, src);
            }
        }
        cp_commit();
    };

    issue(0); issue(1); issue(2);
    for (int ch = 0; ch < 32; ch++) {
        asm volatile("cp.async.wait_group 2;");
        __syncthreads();

        const uint32_t sb = base + (ch & 3) * STAGE2_B;
        uint32_t ah[2][4], al[2][4];
        ldm_x4(ah[0], sb + offA[0]);
        ldm_x4(ah[1], sb + offA[1]);
        ldm_x4(al[0], sb + TILE2_B + offA[0]);
        ldm_x4(al[1], sb + TILE2_B + offA[1]);
#pragma unroll
        for (int p = 0; p < 4; p++) {
            uint32_t bh[4], bl[4];
            ldm_x4(bh, sb + 2 * TILE2_B + offB[p]);
            ldm_x4(bl, sb + 3 * TILE2_B + offB[p]);
#pragma unroll
            for (int mt = 0; mt < 2; mt++) {
                mma_bf16(c[mt][2 * p],     ah[mt][0], ah[mt][1], ah[mt][2], ah[mt][3], bh[0], bh[1]);
                mma_bf16(c[mt][2 * p],     ah[mt][0], ah[mt][1], ah[mt][2], ah[mt][3], bl[0], bl[1]);
                mma_bf16(c[mt][2 * p],     al[mt][0], al[mt][1], al[mt][2], al[mt][3], bh[0], bh[1]);
                mma_bf16(c[mt][2 * p + 1], ah[mt][0], ah[mt][1], ah[mt][2], ah[mt][3], bh[2], bh[3]);
                mma_bf16(c[mt][2 * p + 1], ah[mt][0], ah[mt][1], ah[mt][2], ah[mt][3], bl[2], bl[3]);
                mma_bf16(c[mt][2 * p + 1], al[mt][0], al[mt][1], al[mt][2], al[mt][3], bh[2], bh[3]);
            }
        }
        issue(ch + 3);
    }

    const int r  = lane >> 2;
    const int cq = (lane & 3) * 2;
    const int bb = by >> 3;

    if (bx >= 8) {
        float p[2][2] = {{0.f, 0.f}, {0.f, 0.f}};
#pragma unroll
        for (int nt = 0; nt < 8; nt++) {
            const int lcol = wN * 64 + nt * 8 + cq;
            const float w0 = wf_sm[lcol], w1 = wf_sm[lcol + 1];
            const float b0 = bias_sm[lcol], b1 = bias_sm[lcol + 1];
#pragma unroll
            for (int mt = 0; mt < 2; mt++) {
                p[mt][0] += (c[mt][nt][0] + b0) * w0 + (c[mt][nt][1] + b1) * w1;
                p[mt][1] += (c[mt][nt][2] + b0) * w0 + (c[mt][nt][3] + b1) * w1;
            }
        }
#pragma unroll
        for (int mt = 0; mt < 2; mt++)
#pragma unroll
            for (int rr = 0; rr < 2; rr++) {
                p[mt][rr] += __shfl_xor_sync(0xffffffffu, p[mt][rr], 1);
                p[mt][rr] += __shfl_xor_sync(0xffffffffu, p[mt][rr], 2);
            }
        if ((lane & 3) == 0) {
            const int hh = (bx - 8) * 2 + wN;
#pragma unroll
            for (int mt = 0; mt < 2; mt++)
#pragma unroll
                for (int rr = 0; rr < 2; rr++) {
                    const int grow = by * 128 + wM * 32 + mt * 16 + rr * 8 + r;
                    const int ii = grow & 1023;
                    gVW[(size_t)(bb * NH + hh) * SEQ + ii] = p[mt][rr];
                }
        }
    } else if (bx >= 4) {
#pragma unroll
        for (int nt = 0; nt < 8; nt++) {
            const int lcol = wN * 64 + nt * 8 + cq;
            const int idx = (bx * 128 + lcol) & 511;
            const int h = idx >> 6, w = idx & 63;
            const int ks = w >> 4;
            const int khalf = ks >> 1;
            const int slot = (ks & 1) * 2 + ((w & 15) >> 3);
            const float b0 = bias_sm[lcol], b1 = bias_sm[lcol + 1];
            const int bh = bb * NH + h;
#pragma unroll
            for (int mt = 0; mt < 2; mt++) {
#pragma unroll
                for (int e = 0; e < 2; e++) {
                    const int jb = (by & 7) * 16 + wM * 4 + mt * 2 + e;
                    const size_t addr = (((size_t)bh * 128 + jb) * 2 + khalf) * 128
                                      + lane * 4 + slot;
                    float x0 = c[mt][nt][e * 2]     + b0;
                    float x1 = c[mt][nt][e * 2 + 1] + b1;
                    __nv_bfloat16 h0, l0, h1, l1;
                    split_bf16(x0, h0, l0); split_bf16(x1, h1, l1);
                    gKfh[addr] = pack2(h0, h1);
                    gKfl[addr] = pack2(l0, l1);
                }
            }
        }
    } else {
#pragma unroll
        for (int nt = 0; nt < 8; nt++) {
            const int lcol = wN * 64 + nt * 8 + cq;
            const int idx = (bx * 128 + lcol) & 511;
            const int h = idx >> 6, w = idx & 63;
            const float b0 = bias_sm[lcol], b1 = bias_sm[lcol + 1];
#pragma unroll
            for (int mt = 0; mt < 2; mt++) {
                const int grow = by * 128 + wM * 32 + mt * 16 + r;
                const int ii = grow & 1023;
                size_t dst = (((size_t)(bb * NH + h) * SEQ) + ii) * DH + w;
                float x0 = (c[mt][nt][0] + b0) * SCALEQ;
                float x1 = (c[mt][nt][1] + b1) * SCALEQ;
                float x2 = (c[mt][nt][2] + b0) * SCALEQ;
                float x3 = (c[mt][nt][3] + b1) * SCALEQ;
                __nv_bfloat16 h0, l0, h1, l1, h2, l2, h3, l3;
                split_bf16(x0, h0, l0); split_bf16(x1, h1, l1);
                split_bf16(x2, h2, l2); split_bf16(x3, h3, l3);
                *(uint32_t*)(gQhi + dst) = pack2(h0, h1);
                *(uint32_t*)(gQlo + dst) = pack2(l0, l1);
                *(uint32_t*)(gQhi + dst + (size_t)8 * DH) = pack2(h2, h3);
                *(uint32_t*)(gQlo + dst + (size_t)8 * DH) = pack2(l2, l3);
            }
        }
    }
}

// ============================================================
// K3 (fused): R10 structure, but each warp's 128-j span is
// processed in TWO 64-j phases to cap live accumulators at 64
// floats (no register spills). Phase A stashes exp'd p in fp32
// SMEM; phase B keeps them in registers. Math all-fp32.
// SMEM: wsum  f32[32][1028] : 0..131584
//       Qhi   bf16[32][72]  : 131584..136192
//       Qlo   bf16[32][72]  : 136192..140800
//       vwsm  f32[1024]     : 140800..144896
//       redl  f32[32][8]    : 144896..145920
//       ptile f32[32][516]  : 145920..211968
// ============================================================
#define QS 72
#define WSTRIDE 1028
#define PTS 516
#define FUSED_SMEM 211968

__global__ __launch_bounds__(256, 1) void fused_attn(
    const float* __restrict__ dmask, const float* __restrict__ dirs,
    const float* __restrict__ bf, float* __restrict__ out)
{
    extern __shared__ char sm[];
    float* wsum = (float*)sm;
    __nv_bfloat16* Qhi = (__nv_bfloat16*)(sm + 131584);
    __nv_bfloat16* Qlo = (__nv_bfloat16*)(sm + 136192);
    float* vwsm = (float*)(sm + 140800);
    float* redl = (float*)(sm + 144896);
    float* ptile = (float*)(sm + 145920);

    const int tid = threadIdx.x, wid = tid >> 5, lane = tid & 31;
    const int r = lane >> 2, cq = (lane & 3) * 2;
    const int lr = lane & 7, lg = lane >> 3;
    const int b = blockIdx.x >> 5;
    const int i0 = (blockIdx.x & 31) * 32;
    const int jbase = wid * 128;

    const uint32_t qhiB = smem_u32(Qhi);
    const uint32_t qloB = smem_u32(Qlo);
    uint32_t offQ[2];
#pragma unroll
    for (int mt = 0; mt < 2; mt++) {
        int row = mt * 16 + (lg & 1) * 8 + lr;
        offQ[mt] = row * (QS * 2) + (lg >> 1) * 16;
    }

    for (int idx = tid; idx < 32 * WSTRIDE; idx += 256) wsum[idx] = 0.f;

    for (int h = 0; h < NH; h++) {
        const int bh = b * NH + h;
        __syncthreads();

        // stage Q tile (already split) + vw
        {
            const __nv_bfloat16* Qhb = gQhi + ((size_t)bh * SEQ + i0) * DH;
            const __nv_bfloat16* Qlb = gQlo + ((size_t)bh * SEQ + i0) * DH;
            int row = tid >> 3, cc = tid & 7;
            *(uint4*)(Qhi + row * QS + cc * 8) = *(const uint4*)(Qhb + row * DH + cc * 8);
            *(uint4*)(Qlo + row * QS + cc * 8) = *(const uint4*)(Qlb + row * DH + cc * 8);
            float4 vv = *(const float4*)(gVW + (size_t)bh * SEQ + tid * 4);
            *(float4*)(vwsm + tid * 4) = vv;
        }
        __syncthreads();

        const uint32_t* Kfh = gKfh + (size_t)bh * 128 * 256;
        const uint32_t* Kfl = gKfl + (size_t)bh * 128 * 256;

        float tsum[4] = {0.f, 0.f, 0.f, 0.f};
        float cB[2][8][4];    // phase-B p values (kept in regs)

        // ---------- PHASE A: j-local [0,64), stash p to ptile ----------
        {
            float c[2][8][4];
#pragma unroll
            for (int mt = 0; mt < 2; mt++)
#pragma unroll
                for (int nt = 0; nt < 8; nt++)
#pragma unroll
                    for (int e = 0; e < 4; e++) c[mt][nt][e] = 0.f;

#pragma unroll
            for (int kh2 = 0; kh2 < 2; kh2++) {
                uint32_t ah[2][2][4], al[2][2][4];
#pragma unroll
                for (int ksl = 0; ksl < 2; ksl++) {
                    const uint32_t ko = (kh2 * 2 + ksl) * 32;
#pragma unroll
                    for (int mt = 0; mt < 2; mt++) {
                        ldm_x4(ah[ksl][mt], qhiB + offQ[mt] + ko);
                        ldm_x4(al[ksl][mt], qloB + offQ[mt] + ko);
                    }
                }
#pragma unroll
                for (int nt = 0; nt < 8; nt++) {
                    const int jb = wid * 16 + nt;
                    const size_t fo = ((size_t)jb * 2 + kh2) * 128 + lane * 4;
                    uint4 kh = *(const uint4*)(Kfh + fo);
                    uint4 kl = *(const uint4*)(Kfl + fo);
#pragma unroll
                    for (int mt = 0; mt < 2; mt++) {
                        mma_bf16(c[mt][nt], ah[0][mt][0], ah[0][mt][1], ah[0][mt][2], ah[0][mt][3], kh.x, kh.y);
                        mma_bf16(c[mt][nt], ah[0][mt][0], ah[0][mt][1], ah[0][mt][2], ah[0][mt][3], kl.x, kl.y);
                        mma_bf16(c[mt][nt], al[0][mt][0], al[0][mt][1], al[0][mt][2], al[0][mt][3], kh.x, kh.y);
                        mma_bf16(c[mt][nt], ah[1][mt][0], ah[1][mt][1], ah[1][mt][2], ah[1][mt][3], kh.z, kh.w);
                        mma_bf16(c[mt][nt], ah[1][mt][0], ah[1][mt][1], ah[1][mt][2], ah[1][mt][3], kl.z, kl.w);
                        mma_bf16(c[mt][nt], al[1][mt][0], al[1][mt][1], al[1][mt][2], al[1][mt][3], kh.z, kh.w);
                    }
                }
            }

            // mask + exp + stash (ptile col = wid*64 + nt*8 + cq)
#pragma unroll
            for (int mt = 0; mt < 2; mt++)
#pragma unroll
                for (int half = 0; half < 2; half++) {
                    const int lrow = mt * 16 + half * 8 + r;
                    const size_t rowaddr = ((size_t)bh * SEQ + (i0 + lrow)) * SEQ + jbase + cq;
                    float* prow = ptile + lrow * PTS + wid * 64 + cq;
                    float ts = 0.f;
#pragma unroll
                    for (int nt = 0; nt < 8; nt++) {
                        float2 m = *(const float2*)(dmask + rowaddr + nt * 8);
                        float p0 = __expf(c[mt][nt][half * 2]     + m.x);
                        float p1 = __expf(c[mt][nt][half * 2 + 1] + m.y);
                        ts += p0 + p1;
                        *(float2*)(prow + nt * 8) = make_float2(p0, p1);
                    }
                    tsum[mt * 2 + half] += ts;
                }
        }

        // ---------- PHASE B: j-local [64,128), keep p in regs ----------
        {
#pragma unroll
            for (int mt = 0; mt < 2; mt++)
#pragma unroll
                for (int nt = 0; nt < 8; nt++)
#pragma unroll
                    for (int e = 0; e < 4; e++) cB[mt][nt][e] = 0.f;

#pragma unroll
            for (int kh2 = 0; kh2 < 2; kh2++) {
                uint32_t ah[2][2][4], al[2][2][4];
#pragma unroll
                for (int ksl = 0; ksl < 2; ksl++) {
                    const uint32_t ko = (kh2 * 2 + ksl) * 32;
#pragma unroll
                    for (int mt = 0; mt < 2; mt++) {
                        ldm_x4(ah[ksl][mt], qhiB + offQ[mt] + ko);
                        ldm_x4(al[ksl][mt], qloB + offQ[mt] + ko);
                    }
                }
#pragma unroll
                for (int nt = 0; nt < 8; nt++) {
                    const int jb = wid * 16 + 8 + nt;
                    const size_t fo = ((size_t)jb * 2 + kh2) * 128 + lane * 4;
                    uint4 kh = *(const uint4*)(Kfh + fo);
                    uint4 kl = *(const uint4*)(Kfl + fo);
#pragma unroll
                    for (int mt = 0; mt < 2; mt++) {
                        mma_bf16(cB[mt][nt], ah[0][mt][0], ah[0][mt][1], ah[0][mt][2], ah[0][mt][3], kh.x, kh.y);
                        mma_bf16(cB[mt][nt], ah[0][mt][0], ah[0][mt][1], ah[0][mt][2], ah[0][mt][3], kl.x, kl.y);
                        mma_bf16(cB[mt][nt], al[0][mt][0], al[0][mt][1], al[0][mt][2], al[0][mt][3], kh.x, kh.y);
                        mma_bf16(cB[mt][nt], ah[1][mt][0], ah[1][mt][1], ah[1][mt][2], ah[1][mt][3], kh.z, kh.w);
                        mma_bf16(cB[mt][nt], ah[1][mt][0], ah[1][mt][1], ah[1][mt][2], ah[1][mt][3], kl.z, kl.w);
                        mma_bf16(cB[mt][nt], al[1][mt][0], al[1][mt][1], al[1][mt][2], al[1][mt][3], kh.z, kh.w);
                    }
                }
            }

            // mask + exp (stay in regs)
#pragma unroll
            for (int mt = 0; mt < 2; mt++)
#pragma unroll
                for (int half = 0; half < 2; half++) {
                    const int lrow = mt * 16 + half * 8 + r;
                    const size_t rowaddr = ((size_t)bh * SEQ + (i0 + lrow)) * SEQ + jbase + 64 + cq;
                    float ts = 0.f;
#pragma unroll
                    for (int nt = 0; nt < 8; nt++) {
                        float2 m = *(const float2*)(dmask + rowaddr + nt * 8);
                        float p0 = __expf(cB[mt][nt][half * 2]     + m.x);
                        float p1 = __expf(cB[mt][nt][half * 2 + 1] + m.y);
                        cB[mt][nt][half * 2]     = p0;
                        cB[mt][nt][half * 2 + 1] = p1;
                        ts += p0 + p1;
                    }
                    tsum[mt * 2 + half] += ts;
                }
        }

        // cross-warp row-sum reduction
#pragma unroll
        for (int e = 0; e < 4; e++) {
            tsum[e] += __shfl_xor_sync(0xffffffffu, tsum[e], 1);
            tsum[e] += __shfl_xor_sync(0xffffffffu, tsum[e], 2);
        }
        if ((lane & 3) == 0) {
#pragma unroll
            for (int mt = 0; mt < 2; mt++)
#pragma unroll
                for (int half = 0; half < 2; half++)
                    redl[(mt * 16 + half * 8 + r) * 8 + wid] = tsum[mt * 2 + half];
        }
        __syncthreads();

        float inv[4];
#pragma unroll
        for (int mt = 0; mt < 2; mt++)
#pragma unroll
            for (int half = 0; half < 2; half++) {
                const float* rp = redl + (mt * 16 + half * 8 + r) * 8;
                float ss = rp[0];
#pragma unroll
                for (int w = 1; w < 8; w++) ss += rp[w];
                inv[mt * 2 + half] = 1.0f / ss;
            }

        // wsum update: first half from ptile, second half from cB
#pragma unroll
        for (int nt = 0; nt < 8; nt++) {
            const int jlA = jbase + nt * 8 + cq;
            const int jlB = jlA + 64;
            float2 vwA = *(const float2*)(vwsm + jlA);
            float2 vwB = *(const float2*)(vwsm + jlB);
#pragma unroll
            for (int mt = 0; mt < 2; mt++)
#pragma unroll
                for (int half = 0; half < 2; half++) {
                    const int lrow = mt * 16 + half * 8 + r;
                    const float iv = inv[mt * 2 + half];
                    // phase A (SMEM)
                    {
                        float2 pv = *(float2*)(ptile + lrow * PTS + wid * 64 + nt * 8 + cq
                                               + (half * 2 + mt * 0) * 0);
                        // NOTE: ptile holds p for this (lrow) row directly
                        float* wp = wsum + lrow * WSTRIDE + jlA;
                        float2 w = *(float2*)wp;
                        w.x += pv.x * iv * vwA.x;
                        w.y += pv.y * iv * vwA.y;
                        *(float2*)wp = w;
                    }
                    // phase B (regs)
                    {
                        float* wp = wsum + lrow * WSTRIDE + jlB;
                        float2 w = *(float2*)wp;
                        w.x += cB[mt][nt][half * 2]     * iv * vwB.x;
                        w.y += cB[mt][nt][half * 2 + 1] * iv * vwB.y;
                        *(float2*)wp = w;
                    }
                }
        }
    }
    __syncthreads();

    // dirs contraction: warp wid owns rows 4*wid .. 4*wid+3
    const float bias = bf[0];
#pragma unroll
    for (int rr = 0; rr < 4; rr++) {
        const int ii = wid * 4 + rr;
        const float* dp = dirs + ((size_t)(b * SEQ + i0 + ii)) * SEQ * 3;
        const float* wrow = wsum + ii * WSTRIDE;
        float a0 = 0.f, a1 = 0.f, a2 = 0.f;
#pragma unroll
        for (int t = 0; t < 8; t++) {
            const int jb = (lane + t * 32) * 4;
            const float* dpe = dp + (size_t)jb * 3;
            float4 f0 = *(const float4*)(dpe);
            float4 f1 = *(const float4*)(dpe + 4);
            float4 f2 = *(const float4*)(dpe + 8);
            float4 w4 = *(const float4*)(wrow + jb);
            a0 = fmaf(f0.x, w4.x, a0); a1 = fmaf(f0.y, w4.x, a1); a2 = fmaf(f0.z, w4.x, a2);
            a0 = fmaf(f0.w, w4.y, a0); a1 = fmaf(f1.x, w4.y, a1); a2 = fmaf(f1.y, w4.y, a2);
            a0 = fmaf(f1.z, w4.z, a0); a1 = fmaf(f1.w, w4.z, a1); a2 = fmaf(f2.x, w4.z, a2);
            a0 = fmaf(f2.y, w4.w, a0); a1 = fmaf(f2.z, w4.w, a1); a2 = fmaf(f2.w, w4.w, a2);
        }
#pragma unroll
        for (int o = 16; o; o >>= 1) {
            a0 += __shfl_xor_sync(0xffffffffu, a0, o);
            a1 += __shfl_xor_sync(0xffffffffu, a1, o);
            a2 += __shfl_xor_sync(0xffffffffu, a2, o);
        }
        if (lane == 0) {
            float* op = out + ((size_t)(b * SEQ + i0 + ii)) * 3;
            op[0] = a0 + bias;
            op[1] = a1 + bias;
            op[2] = a2 + bias;
        }
    }
}

// ============================================================
extern "C" void kernel_launch(void* const* d_in, const int* in_sizes, int n_in,
                              void* d_out, int out_size)
{
    const float* emb   = (const float*)d_in[0];  // (4,1024,512)
    const float* dirs  = (const float*)d_in[1];  // (4,1024,1024,3)
    const float* dmask = (const float*)d_in[2];  // (32,1024,1024)
    const float* Wp    = (const float*)d_in[3];  // (512,1536)
    const float* bp    = (const float*)d_in[4];  // (1536,)
    const float* wf    = (const float*)d_in[5];  // (512,)
    const float* bf    = (const float*)d_in[6];  // (1,)
    float* out = (float*)d_out;                  // (4,1024,3)

    cudaFuncSetAttribute(qkv_cp, cudaFuncAttributeMaxDynamicSharedMemorySize, QKV_SMEM);
    cudaFuncSetAttribute(fused_attn, cudaFuncAttributeMaxDynamicSharedMemorySize,
                         FUSED_SMEM);

    prep_all<<<2816, 256>>>(emb, Wp);
    qkv_cp<<<dim3(12, 32), 256, QKV_SMEM>>>(bp, wf);
    fused_attn<<<BATCH * 32, 256, FUSED_SMEM>>>(dmask, dirs, bf, out);
}

// round 17
// speedup vs baseline: 1.1465x; 1.1465x over previous
#include <cuda_runtime.h>
#include <cuda_bf16.h>
#include <stdint.h>
#include <math.h>

#define NH     8
#define BATCH  4
#define SEQ    1024
#define DMODEL 512
#define DH     64
#define SCALEQ 0.04419417382415922f  // 1/sqrt(512)

// ---- scratch (device globals; no allocation allowed) ----
__device__ __nv_bfloat16 gAhi[4096 * 512];   // emb hi
__device__ __nv_bfloat16 gAlo[4096 * 512];   // emb lo
__device__ __nv_bfloat16 gWhi[1536 * 512];   // W^T hi  [n][k]
__device__ __nv_bfloat16 gWlo[1536 * 512];   // W^T lo
__device__ __nv_bfloat16 gQhi[BATCH * NH * SEQ * DH];
__device__ __nv_bfloat16 gQlo[BATCH * NH * SEQ * DH];
// K in mma B-fragment layout: u32[bh][jb(128)][kshalf(2)][lane(32)][slot(4)]
__device__ uint32_t gKfh[BATCH * NH * 128 * 2 * 32 * 4];
__device__ uint32_t gKfl[BATCH * NH * 128 * 2 * 32 * 4];
__device__ float gVW[BATCH * NH * SEQ];

// ============================================================
// helpers
// ============================================================
__device__ __forceinline__ uint32_t smem_u32(const void* p) {
    uint32_t a;
    asm("{ .reg .u64 t; cvta.to.shared.u64 t, %1; cvt.u32.u64 %0, t; }"
        : "=r"(a) : "l"(p));
    return a;
}
__device__ __forceinline__ void split_bf16(float x, __nv_bfloat16& h, __nv_bfloat16& l) {
    h = __float2bfloat16(x);
    l = __float2bfloat16(x - __bfloat162float(h));
}
__device__ __forceinline__ uint32_t pack2(__nv_bfloat16 a, __nv_bfloat16 b) {
    __nv_bfloat162 t; t.x = a; t.y = b;
    return *(uint32_t*)&t;
}
__device__ __forceinline__ void mma_bf16(float c[4], uint32_t a0, uint32_t a1,
                                         uint32_t a2, uint32_t a3,
                                         uint32_t b0, uint32_t b1) {
    asm volatile(
        "mma.sync.aligned.m16n8k16.row.col.f32.bf16.bf16.f32 "
        "{%0,%1,%2,%3}, {%4,%5,%6,%7}, {%8,%9}, {%0,%1,%2,%3};"
        : "+f"(c[0]), "+f"(c[1]), "+f"(c[2]), "+f"(c[3])
        : "r"(a0), "r"(a1), "r"(a2), "r"(a3), "r"(b0), "r"(b1));
}
__device__ __forceinline__ void ldm_x4(uint32_t r[4], uint32_t addr) {
    asm volatile("ldmatrix.sync.aligned.m8n8.x4.shared.b16 {%0,%1,%2,%3}, [%4];"
                 : "=r"(r[0]), "=r"(r[1]), "=r"(r[2]), "=r"(r[3]) : "r"(addr));
}
__device__ __forceinline__ void cp_async16(uint32_t dst, const void* src) {
    asm volatile("cp.async.cg.shared.global [%0], [%1], 16;" :: "r"(dst), "l"(src));
}
__device__ __forceinline__ void cp_commit() {
    asm volatile("cp.async.commit_group;");
}

// ============================================================
// P1 (merged): blocks 0..2047 split emb; blocks 2048..2815
// transpose+split W.
// ============================================================
__global__ __launch_bounds__(256) void prep_all(const float* __restrict__ emb,
                                                const float* __restrict__ W)
{
    if (blockIdx.x < 2048) {
        size_t i = ((size_t)blockIdx.x * 256 + threadIdx.x) * 4;
        float4 v = *(const float4*)(emb + i);
        __nv_bfloat16 h[4], l[4];
        split_bf16(v.x, h[0], l[0]); split_bf16(v.y, h[1], l[1]);
        split_bf16(v.z, h[2], l[2]); split_bf16(v.w, h[3], l[3]);
        uint2 uh = make_uint2(pack2(h[0], h[1]), pack2(h[2], h[3]));
        uint2 ul = make_uint2(pack2(l[0], l[1]), pack2(l[2], l[3]));
        *(uint2*)(gAhi + i) = uh;
        *(uint2*)(gAlo + i) = ul;
    } else {
        __shared__ float t[32][33];
        const int bi = blockIdx.x - 2048;       // 0..767
        const int n0 = (bi % 48) * 32, k0 = (bi / 48) * 32;
        const int tx = threadIdx.x & 31, ty = threadIdx.x >> 5;
#pragma unroll
        for (int it = 0; it < 4; it++)
            t[ty + it * 8][tx] = W[(size_t)(k0 + ty + it * 8) * 1536 + n0 + tx];
        __syncthreads();
#pragma unroll
        for (int it = 0; it < 4; it++) {
            int n = ty + it * 8;
            float v = t[tx][n];
            __nv_bfloat16 h, l;
            split_bf16(v, h, l);
            gWhi[(size_t)(n0 + n) * 512 + k0 + tx] = h;
            gWlo[(size_t)(n0 + n) * 512 + k0 + tx] = l;
        }
    }
}

// ============================================================
// K1: qkv GEMM. 4-stage cp.async ring (BK=16), ONE sync/chunk.
// ============================================================
#define TS2 24
#define TILE2_B (128 * TS2 * 2)          // 6144 B
#define STAGE2_B (4 * TILE2_B)           // 24576 B
#define NSTAGE 4
#define QKV_SMEM (NSTAGE * STAGE2_B + 1024)

__global__ __launch_bounds__(256, 2) void qkv_cp(const float* __restrict__ bias,
                                                 const float* __restrict__ wf)
{
    extern __shared__ char sm[];
    float* bias_sm = (float*)(sm + NSTAGE * STAGE2_B);
    float* wf_sm   = (float*)(sm + NSTAGE * STAGE2_B + 512);
    const uint32_t base = smem_u32(sm);

    const int tid = threadIdx.x;
    const int wid = tid >> 5, lane = tid & 31;
    const int wM = wid & 3, wN = wid >> 2;
    const int bx = blockIdx.x, by = blockIdx.y;
    const int lr = lane & 7, lg = lane >> 3;

    if (tid < 128) {
        bias_sm[tid] = bias[bx * 128 + tid];
        if (bx >= 8) wf_sm[tid] = wf[(bx - 8) * 128 + tid];
    }

    uint32_t offA[2], offB[4];
#pragma unroll
    for (int mt = 0; mt < 2; mt++) {
        int row = wM * 32 + mt * 16 + (lg & 1) * 8 + lr;
        offA[mt] = row * (TS2 * 2) + (lg >> 1) * 16;
    }
#pragma unroll
    for (int p = 0; p < 4; p++) {
        int n = wN * 64 + p * 16 + (lg >> 1) * 8 + lr;
        offB[p] = n * (TS2 * 2) + (lg & 1) * 16;
    }

    const __nv_bfloat16* srcs[4] = {
        gAhi + (size_t)(by * 128) * 512,
        gAlo + (size_t)(by * 128) * 512,
        gWhi + (size_t)(bx * 128) * 512,
        gWlo + (size_t)(bx * 128) * 512
    };

    float c[2][8][4];
#pragma unroll
    for (int mt = 0; mt < 2; mt++)
#pragma unroll
        for (int nt = 0; nt < 8; nt++)
#pragma unroll
            for (int j = 0; j < 4; j++) c[mt][nt][j] = 0.f;

    auto issue = [&](int ch) {
        if (ch < 32) {
            const uint32_t sb = base + (ch & 3) * STAGE2_B;
#pragma unroll
            for (int l = 0; l < 4; l++) {
                int idx = tid + l * 256;
                int tile = idx >> 8;
                int rem = idx & 255;
                int row = rem >> 1, half = rem & 1;
                uint32_t dst = sb + tile * TILE2_B + row * (TS2 * 2) + half * 16;
                const __nv_bfloat16* src = srcs[tile] + (size_t)row * 512 + ch * 16 + half * 8;
                cp_async16(dst, src);
            }
        }
        cp_commit();
    };

    issue(0); issue(1); issue(2);
    for (int ch = 0; ch < 32; ch++) {
        asm volatile("cp.async.wait_group 2;");
        __syncthreads();

        const uint32_t sb = base + (ch & 3) * STAGE2_B;
        uint32_t ah[2][4], al[2][4];
        ldm_x4(ah[0], sb + offA[0]);
        ldm_x4(ah[1], sb + offA[1]);
        ldm_x4(al[0], sb + TILE2_B + offA[0]);
        ldm_x4(al[1], sb + TILE2_B + offA[1]);
#pragma unroll
        for (int p = 0; p < 4; p++) {
            uint32_t bh[4], bl[4];
            ldm_x4(bh, sb + 2 * TILE2_B + offB[p]);
            ldm_x4(bl, sb + 3 * TILE2_B + offB[p]);
#pragma unroll
            for (int mt = 0; mt < 2; mt++) {
                mma_bf16(c[mt][2 * p],     ah[mt][0], ah[mt][1], ah[mt][2], ah[mt][3], bh[0], bh[1]);
                mma_bf16(c[mt][2 * p],     ah[mt][0], ah[mt][1], ah[mt][2], ah[mt][3], bl[0], bl[1]);
                mma_bf16(c[mt][2 * p],     al[mt][0], al[mt][1], al[mt][2], al[mt][3], bh[0], bh[1]);
                mma_bf16(c[mt][2 * p + 1], ah[mt][0], ah[mt][1], ah[mt][2], ah[mt][3], bh[2], bh[3]);
                mma_bf16(c[mt][2 * p + 1], ah[mt][0], ah[mt][1], ah[mt][2], ah[mt][3], bl[2], bl[3]);
                mma_bf16(c[mt][2 * p + 1], al[mt][0], al[mt][1], al[mt][2], al[mt][3], bh[2], bh[3]);
            }
        }
        issue(ch + 3);
    }

    const int r  = lane >> 2;
    const int cq = (lane & 3) * 2;
    const int bb = by >> 3;

    if (bx >= 8) {
        float p[2][2] = {{0.f, 0.f}, {0.f, 0.f}};
#pragma unroll
        for (int nt = 0; nt < 8; nt++) {
            const int lcol = wN * 64 + nt * 8 + cq;
            const float w0 = wf_sm[lcol], w1 = wf_sm[lcol + 1];
            const float b0 = bias_sm[lcol], b1 = bias_sm[lcol + 1];
#pragma unroll
            for (int mt = 0; mt < 2; mt++) {
                p[mt][0] += (c[mt][nt][0] + b0) * w0 + (c[mt][nt][1] + b1) * w1;
                p[mt][1] += (c[mt][nt][2] + b0) * w0 + (c[mt][nt][3] + b1) * w1;
            }
        }
#pragma unroll
        for (int mt = 0; mt < 2; mt++)
#pragma unroll
            for (int rr = 0; rr < 2; rr++) {
                p[mt][rr] += __shfl_xor_sync(0xffffffffu, p[mt][rr], 1);
                p[mt][rr] += __shfl_xor_sync(0xffffffffu, p[mt][rr], 2);
            }
        if ((lane & 3) == 0) {
            const int hh = (bx - 8) * 2 + wN;
#pragma unroll
            for (int mt = 0; mt < 2; mt++)
#pragma unroll
                for (int rr = 0; rr < 2; rr++) {
                    const int grow = by * 128 + wM * 32 + mt * 16 + rr * 8 + r;
                    const int ii = grow & 1023;
                    gVW[(size_t)(bb * NH + hh) * SEQ + ii] = p[mt][rr];
                }
        }
    } else if (bx >= 4) {
#pragma unroll
        for (int nt = 0; nt < 8; nt++) {
            const int lcol = wN * 64 + nt * 8 + cq;
            const int idx = (bx * 128 + lcol) & 511;
            const int h = idx >> 6, w = idx & 63;
            const int ks = w >> 4;
            const int khalf = ks >> 1;
            const int slot = (ks & 1) * 2 + ((w & 15) >> 3);
            const float b0 = bias_sm[lcol], b1 = bias_sm[lcol + 1];
            const int bh = bb * NH + h;
#pragma unroll
            for (int mt = 0; mt < 2; mt++) {
#pragma unroll
                for (int e = 0; e < 2; e++) {
                    const int jb = (by & 7) * 16 + wM * 4 + mt * 2 + e;
                    const size_t addr = (((size_t)bh * 128 + jb) * 2 + khalf) * 128
                                      + lane * 4 + slot;
                    float x0 = c[mt][nt][e * 2]     + b0;
                    float x1 = c[mt][nt][e * 2 + 1] + b1;
                    __nv_bfloat16 h0, l0, h1, l1;
                    split_bf16(x0, h0, l0); split_bf16(x1, h1, l1);
                    gKfh[addr] = pack2(h0, h1);
                    gKfl[addr] = pack2(l0, l1);
                }
            }
        }
    } else {
#pragma unroll
        for (int nt = 0; nt < 8; nt++) {
            const int lcol = wN * 64 + nt * 8 + cq;
            const int idx = (bx * 128 + lcol) & 511;
            const int h = idx >> 6, w = idx & 63;
            const float b0 = bias_sm[lcol], b1 = bias_sm[lcol + 1];
#pragma unroll
            for (int mt = 0; mt < 2; mt++) {
                const int grow = by * 128 + wM * 32 + mt * 16 + r;
                const int ii = grow & 1023;
                size_t dst = (((size_t)(bb * NH + h) * SEQ) + ii) * DH + w;
                float x0 = (c[mt][nt][0] + b0) * SCALEQ;
                float x1 = (c[mt][nt][1] + b1) * SCALEQ;
                float x2 = (c[mt][nt][2] + b0) * SCALEQ;
                float x3 = (c[mt][nt][3] + b1) * SCALEQ;
                __nv_bfloat16 h0, l0, h1, l1, h2, l2, h3, l3;
                split_bf16(x0, h0, l0); split_bf16(x1, h1, l1);
                split_bf16(x2, h2, l2); split_bf16(x3, h3, l3);
                *(uint32_t*)(gQhi + dst) = pack2(h0, h1);
                *(uint32_t*)(gQlo + dst) = pack2(l0, l1);
                *(uint32_t*)(gQhi + dst + (size_t)8 * DH) = pack2(h2, h3);
                *(uint32_t*)(gQlo + dst + (size_t)8 * DH) = pack2(l2, l3);
            }
        }
    }
}

// ============================================================
// K3 (fused): 16-row i-tiles on the lean R13 kernel:
// 256 thr / 8 warps, warp = 16 rows x 128 j (no K redundancy),
// c[16][4] = 64 regs (no spills), 75 KB SMEM -> 2 CTAs/SM,
// grid 256 = one full wave. K fragment-layout (L2-resident).
// SMEM: wsum f32[16][1028] : 0..65792
//       Qhi  bf16[16][72]  : 65792..68096
//       Qlo  bf16[16][72]  : 68096..70400
//       vwsm f32[1024]     : 70400..74496
//       redl f32[16][8]    : 74496..75008
// ============================================================
#define QS 72
#define WSTRIDE 1028
#define FUSED_SMEM 75008

__global__ __launch_bounds__(256, 2) void fused_attn(
    const float* __restrict__ dmask, const float* __restrict__ dirs,
    const float* __restrict__ bf, float* __restrict__ out)
{
    extern __shared__ char sm[];
    float* wsum = (float*)sm;
    __nv_bfloat16* Qhi = (__nv_bfloat16*)(sm + 65792);
    __nv_bfloat16* Qlo = (__nv_bfloat16*)(sm + 68096);
    float* vwsm = (float*)(sm + 70400);
    float* redl = (float*)(sm + 74496);

    const int tid = threadIdx.x, wid = tid >> 5, lane = tid & 31;
    const int r = lane >> 2, cq = (lane & 3) * 2;
    const int lr = lane & 7, lg = lane >> 3;
    const int b = blockIdx.x >> 6;
    const int i0 = (blockIdx.x & 63) * 16;
    const int jbase = wid * 128;

    const uint32_t qhiB = smem_u32(Qhi);
    const uint32_t qloB = smem_u32(Qlo);
    const uint32_t offQ = ((lg & 1) * 8 + lr) * (QS * 2) + (lg >> 1) * 16;

    for (int idx = tid; idx < 16 * WSTRIDE; idx += 256) wsum[idx] = 0.f;

    for (int h = 0; h < NH; h++) {
        const int bh = b * NH + h;
        __syncthreads();

        // stage Q tile (tid<128) + vw (all threads)
        {
            if (tid < 128) {
                const __nv_bfloat16* Qhb = gQhi + ((size_t)bh * SEQ + i0) * DH;
                const __nv_bfloat16* Qlb = gQlo + ((size_t)bh * SEQ + i0) * DH;
                int row = tid >> 3, cc = tid & 7;
                *(uint4*)(Qhi + row * QS + cc * 8) = *(const uint4*)(Qhb + row * DH + cc * 8);
                *(uint4*)(Qlo + row * QS + cc * 8) = *(const uint4*)(Qlb + row * DH + cc * 8);
            }
            float4 vv = *(const float4*)(gVW + (size_t)bh * SEQ + tid * 4);
            *(float4*)(vwsm + tid * 4) = vv;
        }
        __syncthreads();

        // S(16 x 128 per warp) = Q @ K^T; K via coalesced uint4 fragments
        float c[16][4];
#pragma unroll
        for (int nt = 0; nt < 16; nt++)
#pragma unroll
            for (int e = 0; e < 4; e++) c[nt][e] = 0.f;

        const uint32_t* Kfh = gKfh + (size_t)bh * 128 * 256;
        const uint32_t* Kfl = gKfl + (size_t)bh * 128 * 256;
#pragma unroll
        for (int kh2 = 0; kh2 < 2; kh2++) {
            uint32_t ah[2][4], al[2][4];       // [ks-in-half][4]
#pragma unroll
            for (int ksl = 0; ksl < 2; ksl++) {
                const uint32_t ko = (kh2 * 2 + ksl) * 32;
                ldm_x4(ah[ksl], qhiB + offQ + ko);
                ldm_x4(al[ksl], qloB + offQ + ko);
            }
#pragma unroll
            for (int nt = 0; nt < 16; nt++) {
                const int jb = wid * 16 + nt;
                const size_t fo = ((size_t)jb * 2 + kh2) * 128 + lane * 4;
                uint4 kh = *(const uint4*)(Kfh + fo);
                uint4 kl = *(const uint4*)(Kfl + fo);
                mma_bf16(c[nt], ah[0][0], ah[0][1], ah[0][2], ah[0][3], kh.x, kh.y);
                mma_bf16(c[nt], ah[0][0], ah[0][1], ah[0][2], ah[0][3], kl.x, kl.y);
                mma_bf16(c[nt], al[0][0], al[0][1], al[0][2], al[0][3], kh.x, kh.y);
                mma_bf16(c[nt], ah[1][0], ah[1][1], ah[1][2], ah[1][3], kh.z, kh.w);
                mma_bf16(c[nt], ah[1][0], ah[1][1], ah[1][2], ah[1][3], kl.z, kl.w);
                mma_bf16(c[nt], al[1][0], al[1][1], al[1][2], al[1][3], kh.z, kh.w);
            }
        }

        // mask add + exp + row sum
        float tsum[2] = {0.f, 0.f};
#pragma unroll
        for (int half = 0; half < 2; half++) {
            const int lrow = half * 8 + r;
            const size_t rowaddr = ((size_t)bh * SEQ + (i0 + lrow)) * SEQ + jbase + cq;
            float ts = 0.f;
#pragma unroll
            for (int nt = 0; nt < 16; nt++) {
                float2 m = *(const float2*)(dmask + rowaddr + nt * 8);
                float p0 = __expf(c[nt][half * 2]     + m.x);
                float p1 = __expf(c[nt][half * 2 + 1] + m.y);
                c[nt][half * 2]     = p0;
                c[nt][half * 2 + 1] = p1;
                ts += p0 + p1;
            }
            tsum[half] = ts;
        }
#pragma unroll
        for (int e = 0; e < 2; e++) {
            tsum[e] += __shfl_xor_sync(0xffffffffu, tsum[e], 1);
            tsum[e] += __shfl_xor_sync(0xffffffffu, tsum[e], 2);
        }
        if ((lane & 3) == 0) {
#pragma unroll
            for (int half = 0; half < 2; half++)
                redl[(half * 8 + r) * 8 + wid] = tsum[half];
        }
        __syncthreads();

        float inv[2];
#pragma unroll
        for (int half = 0; half < 2; half++) {
            const float* rp = redl + (half * 8 + r) * 8;
            float ss = rp[0];
#pragma unroll
            for (int w = 1; w < 8; w++) ss += rp[w];
            inv[half] = 1.0f / ss;
        }

        // wsum += attn * vw (warps own disjoint j slices)
#pragma unroll
        for (int nt = 0; nt < 16; nt++) {
            const int jl = jbase + nt * 8 + cq;
            float2 vw2 = *(const float2*)(vwsm + jl);
#pragma unroll
            for (int half = 0; half < 2; half++) {
                const int lrow = half * 8 + r;
                float* wp = wsum + lrow * WSTRIDE + jl;
                float2 w = *(float2*)wp;
                float iv = inv[half];
                w.x += c[nt][half * 2]     * iv * vw2.x;
                w.y += c[nt][half * 2 + 1] * iv * vw2.y;
                *(float2*)wp = w;
            }
        }
    }
    __syncthreads();

    // dirs contraction: warp wid owns rows 2*wid .. 2*wid+1
    const float bias = bf[0];
#pragma unroll
    for (int rr = 0; rr < 2; rr++) {
        const int ii = wid * 2 + rr;
        const float* dp = dirs + ((size_t)(b * SEQ + i0 + ii)) * SEQ * 3;
        const float* wrow = wsum + ii * WSTRIDE;
        float a0 = 0.f, a1 = 0.f, a2 = 0.f;
#pragma unroll
        for (int t = 0; t < 8; t++) {
            const int jb = (lane + t * 32) * 4;
            const float* dpe = dp + (size_t)jb * 3;
            float4 f0 = *(const float4*)(dpe);
            float4 f1 = *(const float4*)(dpe + 4);
            float4 f2 = *(const float4*)(dpe + 8);
            float4 w4 = *(const float4*)(wrow + jb);
            a0 = fmaf(f0.x, w4.x, a0); a1 = fmaf(f0.y, w4.x, a1); a2 = fmaf(f0.z, w4.x, a2);
            a0 = fmaf(f0.w, w4.y, a0); a1 = fmaf(f1.x, w4.y, a1); a2 = fmaf(f1.y, w4.y, a2);
            a0 = fmaf(f1.z, w4.z, a0); a1 = fmaf(f1.w, w4.z, a1); a2 = fmaf(f2.x, w4.z, a2);
            a0 = fmaf(f2.y, w4.w, a0); a1 = fmaf(f2.z, w4.w, a1); a2 = fmaf(f2.w, w4.w, a2);
        }
#pragma unroll
        for (int o = 16; o; o >>= 1) {
            a0 += __shfl_xor_sync(0xffffffffu, a0, o);
            a1 += __shfl_xor_sync(0xffffffffu, a1, o);
            a2 += __shfl_xor_sync(0xffffffffu, a2, o);
        }
        if (lane == 0) {
            float* op = out + ((size_t)(b * SEQ + i0 + ii)) * 3;
            op[0] = a0 + bias;
            op[1] = a1 + bias;
            op[2] = a2 + bias;
        }
    }
}

// ============================================================
extern "C" void kernel_launch(void* const* d_in, const int* in_sizes, int n_in,
                              void* d_out, int out_size)
{
    const float* emb   = (const float*)d_in[0];  // (4,1024,512)
    const float* dirs  = (const float*)d_in[1];  // (4,1024,1024,3)
    const float* dmask = (const float*)d_in[2];  // (32,1024,1024)
    const float* Wp    = (const float*)d_in[3];  // (512,1536)
    const float* bp    = (const float*)d_in[4];  // (1536,)
    const float* wf    = (const float*)d_in[5];  // (512,)
    const float* bf    = (const float*)d_in[6];  // (1,)
    float* out = (float*)d_out;                  // (4,1024,3)

    cudaFuncSetAttribute(qkv_cp, cudaFuncAttributeMaxDynamicSharedMemorySize, QKV_SMEM);
    cudaFuncSetAttribute(fused_attn, cudaFuncAttributeMaxDynamicSharedMemorySize,
                         FUSED_SMEM);

    prep_all<<<2816, 256>>>(emb, Wp);
    qkv_cp<<<dim3(12, 32), 256, QKV_SMEM>>>(bp, wf);
    fused_attn<<<BATCH * 64, 256, FUSED_SMEM>>>(dmask, dirs, bf, out);
}